// round 10
// baseline (speedup 1.0000x reference)
#include <cuda_runtime.h>
#include <cuda_fp16.h>
#include <cstdint>

#define NN 74240
#define EE 593920
#define DD 128
#define NLAYERS 3
#define EPS_BN 1e-5f

// ---------------- scratch ----------------
__device__ float g_h[NN * DD];
__device__ float g_tmp[NN * DD];
__device__ float g_sum[NLAYERS * DD];
__device__ float g_sumsq[NLAYERS * DD];
__device__ __half g_Wth[NLAYERS * DD * DD];    // GraphConv W, fp16-rn, [l][n][k]
__device__ float g_Wt[NLAYERS * DD * DD];      // Residual W, tf32-rna, [l][n][k]
__device__ int g_deg[NN];
__device__ int g_off[NN + 1];
__device__ int g_pos[NN];
__device__ int g_csr[EE];
__device__ unsigned g_scanst[160];

// ---------------- helpers ----------------
__device__ __forceinline__ uint32_t smem_u32(const void* p) {
    uint32_t a;
    asm("{ .reg .u64 t; cvta.to.shared.u64 t, %1; cvt.u32.u64 %0, t; }" : "=r"(a) : "l"(p));
    return a;
}
__device__ __forceinline__ void cp16(uint32_t dst, const void* src) {
    asm volatile("cp.async.cg.shared.global [%0], [%1], 16;" :: "r"(dst), "l"(src));
}
#define CP_COMMIT() asm volatile("cp.async.commit_group;" ::: "memory")
#define CP_WAIT(n)  asm volatile("cp.async.wait_group %0;" :: "n"(n) : "memory")

__device__ __forceinline__ void ldsm_x4(uint32_t* r, uint32_t addr) {
    asm volatile("ldmatrix.sync.aligned.m8n8.x4.shared.b16 {%0,%1,%2,%3}, [%4];"
                 : "=r"(r[0]), "=r"(r[1]), "=r"(r[2]), "=r"(r[3]) : "r"(addr));
}
__device__ __forceinline__ void mma_tf32(float* c, const uint32_t* a, const uint32_t* b) {
    asm volatile(
        "mma.sync.aligned.m16n8k8.row.col.f32.tf32.tf32.f32 "
        "{%0,%1,%2,%3}, {%4,%5,%6,%7}, {%8,%9}, {%0,%1,%2,%3};"
        : "+f"(c[0]), "+f"(c[1]), "+f"(c[2]), "+f"(c[3])
        : "r"(a[0]), "r"(a[1]), "r"(a[2]), "r"(a[3]), "r"(b[0]), "r"(b[1]));
}
__device__ __forceinline__ void mma_f16(float* c, const uint32_t* a, const uint32_t* b) {
    asm volatile(
        "mma.sync.aligned.m16n8k16.row.col.f32.f16.f16.f32 "
        "{%0,%1,%2,%3}, {%4,%5,%6,%7}, {%8,%9}, {%0,%1,%2,%3};"
        : "+f"(c[0]), "+f"(c[1]), "+f"(c[2]), "+f"(c[3])
        : "r"(a[0]), "r"(a[1]), "r"(a[2]), "r"(a[3]), "r"(b[0]), "r"(b[1]));
}
__device__ __forceinline__ void split_tf32(float v, uint32_t& hi, uint32_t& lo) {
    asm("cvt.rna.tf32.f32 %0, %1;" : "=r"(hi) : "f"(v));
    float r = v - __uint_as_float(hi);
    asm("cvt.rna.tf32.f32 %0, %1;" : "=r"(lo) : "f"(r));
}

// ============================================================================
// small prep kernels
// ============================================================================
__global__ void __launch_bounds__(256) k_zero() {
    int i = blockIdx.x * 256 + threadIdx.x;
    if (i < NN) g_deg[i] = 0;
    if (i < NLAYERS * DD) { g_sum[i] = 0.f; g_sumsq[i] = 0.f; }
    if (i < 160) g_scanst[i] = 0u;
}
__global__ void __launch_bounds__(256) k_prep_w(const float* __restrict__ Wg,
                                                const float* __restrict__ Wr) {
    int gid = blockIdx.x * 256 + threadIdx.x;     // 0..98303
    int mat6 = gid >> 14;
    int e = gid & 16383;
    int n = e >> 7, k = e & 127;
    int l = mat6 >> 1, op = mat6 & 1;
    const float* src = (op ? Wr : Wg) + l * DD * DD;
    float v = src[k * 128 + n];
    if (op == 0) {
        g_Wth[l * 16384 + n * 128 + k] = __float2half_rn(v);
    } else {
        uint32_t u;
        asm("cvt.rna.tf32.f32 %0, %1;" : "=r"(u) : "f"(v));
        g_Wt[l * 16384 + n * 128 + k] = __uint_as_float(u);
    }
}
__global__ void __launch_bounds__(256) k_hist(const int* __restrict__ dst) {
    int e = blockIdx.x * 256 + threadIdx.x;
    if (e < EE) atomicAdd(&g_deg[dst[e]], 1);
}
__global__ void __launch_bounds__(512) k_scan_lb() {
    __shared__ int ws[16];
    __shared__ unsigned sprefix;
    int tid = threadIdx.x;
    int lane = tid & 31, w = tid >> 5;
    int gi = blockIdx.x * 512 + tid;
    int v = g_deg[gi];
    int x = v;
#pragma unroll
    for (int o = 1; o < 32; o <<= 1) {
        int t = __shfl_up_sync(0xffffffff, x, o);
        if (lane >= o) x += t;
    }
    if (lane == 31) ws[w] = x;
    __syncthreads();
    if (w == 0) {
        int y = (lane < 16) ? ws[lane] : 0;
#pragma unroll
        for (int o = 1; o < 16; o <<= 1) {
            int t = __shfl_up_sync(0xffffffff, y, o);
            if (lane >= o) y += t;
        }
        if (lane < 16) ws[lane] = y;
    }
    __syncthreads();
    int base = (w > 0) ? ws[w - 1] : 0;
    int excl = base + x - v;
    int btot = ws[15];
    if (tid == 0) {
        unsigned pub = ((blockIdx.x == 0 ? 2u : 1u) << 30) | (unsigned)btot;
        atomicExch(&g_scanst[blockIdx.x], pub);
        unsigned pre = 0;
        if (blockIdx.x > 0) {
            int i = blockIdx.x - 1;
            while (true) {
                unsigned s;
                do { s = atomicAdd(&g_scanst[i], 0u); } while (s == 0u);
                pre += s & 0x3FFFFFFFu;
                if ((s >> 30) == 2u) break;
                i--;
            }
            atomicExch(&g_scanst[blockIdx.x], (2u << 30) | (pre + (unsigned)btot));
        }
        sprefix = pre;
    }
    __syncthreads();
    int off = (int)sprefix + excl;
    g_off[gi] = off;
    g_pos[gi] = off;
    if (gi == 0) g_off[NN] = EE;
}
__global__ void __launch_bounds__(256) k_fill(const int* __restrict__ src,
                                              const int* __restrict__ dst) {
    int e = blockIdx.x * 256 + threadIdx.x;
    if (e < EE) {
        int p = atomicAdd(&g_pos[dst[e]], 1);
        g_csr[p] = src[e];
    }
}

// ============================================================================
// init GEMM, split-tf32 (3-term compensation; ~fp32): g_h = X[NN,75] @ W[75,128]
// ============================================================================
#define IXS 44
#define IWS 132
__global__ void __launch_bounds__(256) k_init_tf32(const float* __restrict__ X,
                                                   const float* __restrict__ W) {
    __shared__ float Xs[128 * IXS];
    __shared__ float Ws[40 * IWS];
    int tid = threadIdx.x;
    int lane = tid & 31;
    int wid = tid >> 5;
    int mwarp = wid & 3, nwarp = wid >> 2;
    int rowBase = blockIdx.x * 128;
    int mBase = mwarp * 32, nBase = nwarp * 64;
    int frow = lane >> 2, fcol = lane & 3;

    float acc[2][8][4];
#pragma unroll
    for (int mt = 0; mt < 2; mt++)
#pragma unroll
        for (int nt = 0; nt < 8; nt++)
#pragma unroll
            for (int j = 0; j < 4; j++) acc[mt][nt][j] = 0.f;

    for (int k0 = 0; k0 < 80; k0 += 40) {
        for (int idx = tid; idx < 128 * 40; idx += 256) {
            int r = idx / 40, k = idx - r * 40;
            int gk = k0 + k;
            Xs[r * IXS + k] = (gk < 75) ? X[(rowBase + r) * 75 + gk] : 0.f;
        }
        for (int idx = tid; idx < 40 * 128; idx += 256) {
            int k = idx >> 7, n = idx & 127;
            int gk = k0 + k;
            Ws[k * IWS + n] = (gk < 75) ? W[gk * 128 + n] : 0.f;
        }
        __syncthreads();
#pragma unroll
        for (int kb = 0; kb < 40; kb += 8) {
            uint32_t ahi[2][4], alo[2][4];
#pragma unroll
            for (int mt = 0; mt < 2; mt++) {
                int r0 = mBase + mt * 16 + frow;
                split_tf32(Xs[r0 * IXS + kb + fcol],           ahi[mt][0], alo[mt][0]);
                split_tf32(Xs[(r0 + 8) * IXS + kb + fcol],     ahi[mt][1], alo[mt][1]);
                split_tf32(Xs[r0 * IXS + kb + fcol + 4],       ahi[mt][2], alo[mt][2]);
                split_tf32(Xs[(r0 + 8) * IXS + kb + fcol + 4], ahi[mt][3], alo[mt][3]);
            }
            uint32_t bhi[8][2], blo[8][2];
#pragma unroll
            for (int nt = 0; nt < 8; nt++) {
                int n = nBase + nt * 8 + frow;
                split_tf32(Ws[(kb + fcol) * IWS + n],     bhi[nt][0], blo[nt][0]);
                split_tf32(Ws[(kb + fcol + 4) * IWS + n], bhi[nt][1], blo[nt][1]);
            }
#pragma unroll
            for (int mt = 0; mt < 2; mt++)
#pragma unroll
                for (int nt = 0; nt < 8; nt++) {
                    mma_tf32(acc[mt][nt], ahi[mt], bhi[nt]);
                    mma_tf32(acc[mt][nt], alo[mt], bhi[nt]);
                    mma_tf32(acc[mt][nt], ahi[mt], blo[nt]);
                }
        }
        __syncthreads();
    }
#pragma unroll
    for (int mt = 0; mt < 2; mt++)
#pragma unroll
        for (int nt = 0; nt < 8; nt++) {
            int col = nBase + nt * 8 + fcol * 2;
            int r0 = rowBase + mBase + mt * 16 + frow;
            *(float2*)&g_h[r0 * 128 + col]       = make_float2(acc[mt][nt][0], acc[mt][nt][1]);
            *(float2*)&g_h[(r0 + 8) * 128 + col] = make_float2(acc[mt][nt][2], acc[mt][nt][3]);
        }
}

// ============================================================================
// Merged layer kernel (gather + dual GEMM + stats):
//   A1[i] = fp16( s * sum_{src in-edges(rowBase+i)} x[src] + deg*t )   (in smem)
//   C = relu(A1 @ W1h + b1) + relu( (s*x + t) @ W2 + b2 ) + BN stats
// smem: A1 full [128 x 272B fp16] | W1h full [128 x 272B fp16] |
//       2-stage pipeline {A2 [128x144B f32] | W2 [128x144B f32]} | bias/aff
// ============================================================================
#define SM_A1   0
#define SM_W1   34816
#define SM_PIPE 69632
#define PSTG_B  36864           // A2 (18432) + W2 (18432)
#define PA2_OFF 0
#define PW2_OFF 18432
#define BIAS1_F ((SM_PIPE + 2 * PSTG_B) / 4)    // 35840
#define BIAS2_F (BIAS1_F + 128)
#define AFF_F   (BIAS2_F + 128)
#define SMEM_FUSED (SM_PIPE + 2 * PSTG_B + 512 + 512 + 1024)

__device__ __forceinline__ void issue_pipe_chunk(uint32_t sb, int st, int c, int tid,
                                                 int rowBase, const float* A2,
                                                 const float* W2t) {
    uint32_t stb = sb + SM_PIPE + st * PSTG_B;
    int k0 = c * 32;
#pragma unroll
    for (int i = 0; i < 4; i++) {
        int idx = i * 256 + tid;
        int r = idx >> 3, q = idx & 7;
        uint32_t soff = r * 144 + q * 16;
        int goff = k0 + q * 4;
        cp16(stb + PA2_OFF + soff, A2 + (rowBase + r) * 128 + goff);
        cp16(stb + PW2_OFF + soff, W2t + r * 128 + goff);
    }
}

__device__ __forceinline__ void compute_chunk(uint32_t sb, int st, int k0,
                                              int mBase, int nBase, int lane,
                                              const float2* affS,
                                              float acc1[2][8][4], float acc2[2][8][4]) {
    uint32_t stb = sb + SM_PIPE + st * PSTG_B;
    int g = lane >> 3, lr = lane & 7;
    int fcol = lane & 3;
    int arow = ((g & 1) << 3) + lr;
    int abyte = (g >> 1) << 4;
    int brow = ((g >> 1) << 3) + lr;
    int bbyte = (g & 1) << 4;

    // ---- GC branch: fp16 k16 MMAs from full-K single-buffer tiles ----
#pragma unroll
    for (int kb = 0; kb < 32; kb += 16) {
        int kk = k0 + kb;
        uint32_t a1[2][4];
#pragma unroll
        for (int mt = 0; mt < 2; mt++) {
            uint32_t base = sb + SM_A1 + (uint32_t)(mBase + mt * 16 + arow) * 272 + kk * 2 + abyte;
            ldsm_x4(a1[mt], base);
        }
        uint32_t bf[4][4];
#pragma unroll
        for (int p = 0; p < 4; p++) {
            uint32_t base = sb + SM_W1 + (uint32_t)(nBase + p * 16 + brow) * 272 + kk * 2 + bbyte;
            ldsm_x4(bf[p], base);
        }
#pragma unroll
        for (int mt = 0; mt < 2; mt++)
#pragma unroll
            for (int p = 0; p < 4; p++) {
                mma_f16(acc1[mt][2 * p],     a1[mt], &bf[p][0]);
                mma_f16(acc1[mt][2 * p + 1], a1[mt], &bf[p][2]);
            }
    }

    // ---- RES branch: tf32 k8 MMAs, BN affine applied to A2 fragments ----
#pragma unroll
    for (int kb = 0; kb < 32; kb += 8) {
        uint32_t a2[2][4];
#pragma unroll
        for (int mt = 0; mt < 2; mt++) {
            uint32_t base = stb + PA2_OFF + (uint32_t)(mBase + mt * 16 + arow) * 144 + kb * 4 + abyte;
            ldsm_x4(a2[mt], base);
        }
        float2 f0 = affS[k0 + kb + fcol];
        float2 f4 = affS[k0 + kb + fcol + 4];
#pragma unroll
        for (int mt = 0; mt < 2; mt++) {
            a2[mt][0] = __float_as_uint(fmaf(f0.x, __uint_as_float(a2[mt][0]), f0.y));
            a2[mt][1] = __float_as_uint(fmaf(f0.x, __uint_as_float(a2[mt][1]), f0.y));
            a2[mt][2] = __float_as_uint(fmaf(f4.x, __uint_as_float(a2[mt][2]), f4.y));
            a2[mt][3] = __float_as_uint(fmaf(f4.x, __uint_as_float(a2[mt][3]), f4.y));
        }
        uint32_t b2[4][4];
#pragma unroll
        for (int p = 0; p < 4; p++) {
            uint32_t base = stb + PW2_OFF + (uint32_t)(nBase + p * 16 + brow) * 144 + kb * 4 + bbyte;
            ldsm_x4(b2[p], base);
        }
#pragma unroll
        for (int mt = 0; mt < 2; mt++)
#pragma unroll
            for (int p = 0; p < 4; p++) {
                mma_tf32(acc2[mt][2 * p],     a2[mt], &b2[p][0]);
                mma_tf32(acc2[mt][2 * p + 1], a2[mt], &b2[p][2]);
            }
    }
}

__global__ void __launch_bounds__(256, 1) k_layer_fused(
    const float* __restrict__ xin,
    const __half* __restrict__ W1h, const float* __restrict__ W2t,
    const float* __restrict__ b1, const float* __restrict__ b2,
    const float* __restrict__ sumPrev, const float* __restrict__ sumsqPrev,
    const float* __restrict__ gammaPrev, const float* __restrict__ betaPrev, int useAff,
    float* __restrict__ C, float* __restrict__ sumP, float* __restrict__ sumsqP) {
    extern __shared__ char smc[];
    float* smf = (float*)smc;
    uint32_t sb = smem_u32(smc);
    int tid = threadIdx.x;
    int lane = tid & 31;
    int wid = tid >> 5;
    int mwarp = wid & 3, nwarp = wid >> 2;
    int rowBase = blockIdx.x * 128;
    int mBase = mwarp * 32, nBase = nwarp * 64;
    int frow = lane >> 2, fcol = lane & 3;

    // bias + BN affine (of previous layer) to smem
    if (tid < 128) {
        smf[BIAS1_F + tid] = b1[tid];
        smf[BIAS2_F + tid] = b2[tid];
        float2 a = make_float2(1.f, 0.f);
        if (useAff) {
            const float invN = 1.f / (float)NN;
            float mu = sumPrev[tid] * invN;
            float var = sumsqPrev[tid] * invN - mu * mu;
            float s = gammaPrev[tid] * rsqrtf(var + EPS_BN);
            a = make_float2(s, betaPrev[tid] - mu * s);
        }
        ((float2*)(smf + AFF_F))[tid] = a;
    }
    const float2* affS = (const float2*)(smf + AFF_F);

    // issue W1h full tile (fp16, 128 rows x 256B) + pipeline chunks 0,1
    {
#pragma unroll
        for (int i = 0; i < 8; i++) {
            int idx = i * 256 + tid;
            int r = idx >> 4, q = idx & 15;
            cp16(sb + SM_W1 + r * 272 + q * 16, W1h + r * 128 + q * 8);
        }
        issue_pipe_chunk(sb, 0, 0, tid, rowBase, xin, W2t);
        CP_COMMIT();                      // group0 = W1 full + chunk0
        issue_pipe_chunk(sb, 1, 1, tid, rowBase, xin, W2t);
        CP_COMMIT();                      // group1 = chunk1
    }

    __syncthreads();   // affS visible to all threads for the gather

    // ---- in-CTA gather: each warp fills 16 rows of A1 (fp16) ----
    {
        int lo4 = lane * 4;
        float2 a0 = affS[lo4], a1f = affS[lo4 + 1], a2f = affS[lo4 + 2], a3f = affS[lo4 + 3];
        for (int t = 0; t < 16; t++) {
            int i = wid * 16 + t;
            int node = rowBase + i;
            int beg = g_off[node], end = g_off[node + 1];
            float4 acc0 = make_float4(0.f, 0.f, 0.f, 0.f);
            float4 acc1v = make_float4(0.f, 0.f, 0.f, 0.f);
            float4 acc2v = make_float4(0.f, 0.f, 0.f, 0.f);
            float4 acc3v = make_float4(0.f, 0.f, 0.f, 0.f);
            for (int base = beg; base < end; base += 32) {
                int ii = base + lane;
                int idx = (ii < end) ? __ldg(&g_csr[ii]) : 0;
                int cnt = min(32, end - base);
                int j = 0;
                for (; j + 4 <= cnt; j += 4) {
                    int s0 = __shfl_sync(0xffffffff, idx, j);
                    int s1 = __shfl_sync(0xffffffff, idx, j + 1);
                    int s2 = __shfl_sync(0xffffffff, idx, j + 2);
                    int s3 = __shfl_sync(0xffffffff, idx, j + 3);
                    float4 v0 = *(const float4*)&xin[s0 * 128 + lo4];
                    float4 v1 = *(const float4*)&xin[s1 * 128 + lo4];
                    float4 v2 = *(const float4*)&xin[s2 * 128 + lo4];
                    float4 v3 = *(const float4*)&xin[s3 * 128 + lo4];
                    acc0.x += v0.x; acc0.y += v0.y; acc0.z += v0.z; acc0.w += v0.w;
                    acc1v.x += v1.x; acc1v.y += v1.y; acc1v.z += v1.z; acc1v.w += v1.w;
                    acc2v.x += v2.x; acc2v.y += v2.y; acc2v.z += v2.z; acc2v.w += v2.w;
                    acc3v.x += v3.x; acc3v.y += v3.y; acc3v.z += v3.z; acc3v.w += v3.w;
                }
                for (; j < cnt; j++) {
                    int s = __shfl_sync(0xffffffff, idx, j);
                    float4 v = *(const float4*)&xin[s * 128 + lo4];
                    acc0.x += v.x; acc0.y += v.y; acc0.z += v.z; acc0.w += v.w;
                }
            }
            acc0.x += acc1v.x + acc2v.x + acc3v.x;
            acc0.y += acc1v.y + acc2v.y + acc3v.y;
            acc0.z += acc1v.z + acc2v.z + acc3v.z;
            acc0.w += acc1v.w + acc2v.w + acc3v.w;
            float deg = (float)(end - beg);
            float o0 = a0.x * acc0.x + deg * a0.y;
            float o1 = a1f.x * acc0.y + deg * a1f.y;
            float o2 = a2f.x * acc0.z + deg * a2f.y;
            float o3 = a3f.x * acc0.w + deg * a3f.y;
            __half2 p0 = __floats2half2_rn(o0, o1);
            __half2 p1 = __floats2half2_rn(o2, o3);
            uint2 pk;
            pk.x = *(uint32_t*)&p0;
            pk.y = *(uint32_t*)&p1;
            *(uint2*)(smc + SM_A1 + i * 272 + lane * 8) = pk;
        }
    }
    __syncthreads();   // A1 complete

    float acc1[2][8][4], acc2[2][8][4];
#pragma unroll
    for (int mt = 0; mt < 2; mt++)
#pragma unroll
        for (int nt = 0; nt < 8; nt++)
#pragma unroll
            for (int j = 0; j < 4; j++) { acc1[mt][nt][j] = 0.f; acc2[mt][nt][j] = 0.f; }

    CP_WAIT(1); __syncthreads();       // W1 full + chunk0 ready
    compute_chunk(sb, 0, 0, mBase, nBase, lane, affS, acc1, acc2);
    __syncthreads();
    issue_pipe_chunk(sb, 0, 2, tid, rowBase, xin, W2t); CP_COMMIT();

    CP_WAIT(1); __syncthreads();
    compute_chunk(sb, 1, 32, mBase, nBase, lane, affS, acc1, acc2);
    __syncthreads();
    issue_pipe_chunk(sb, 1, 3, tid, rowBase, xin, W2t); CP_COMMIT();

    CP_WAIT(1); __syncthreads();
    compute_chunk(sb, 0, 64, mBase, nBase, lane, affS, acc1, acc2);
    __syncthreads();

    CP_WAIT(0); __syncthreads();
    compute_chunk(sb, 1, 96, mBase, nBase, lane, affS, acc1, acc2);

    // epilogue: bias + relu + sum, store pre-BN x, BN column partial stats
    const float* bs1 = smf + BIAS1_F;
    const float* bs2 = smf + BIAS2_F;
#pragma unroll
    for (int nt = 0; nt < 8; nt++) {
        int col = nBase + nt * 8 + fcol * 2;
        float B10 = bs1[col], B11 = bs1[col + 1];
        float B20 = bs2[col], B21 = bs2[col + 1];
        float s0 = 0.f, s1 = 0.f, q0 = 0.f, q1 = 0.f;
#pragma unroll
        for (int mt = 0; mt < 2; mt++) {
            int r0 = rowBase + mBase + mt * 16 + frow;
            int r1 = r0 + 8;
            float u0 = acc1[mt][nt][0] + B10; u0 = u0 > 0.f ? u0 : 0.f;
            float u1 = acc1[mt][nt][1] + B11; u1 = u1 > 0.f ? u1 : 0.f;
            float u2 = acc1[mt][nt][2] + B10; u2 = u2 > 0.f ? u2 : 0.f;
            float u3 = acc1[mt][nt][3] + B11; u3 = u3 > 0.f ? u3 : 0.f;
            float v0 = acc2[mt][nt][0] + B20; v0 = v0 > 0.f ? v0 : 0.f;
            float v1 = acc2[mt][nt][1] + B21; v1 = v1 > 0.f ? v1 : 0.f;
            float v2 = acc2[mt][nt][2] + B20; v2 = v2 > 0.f ? v2 : 0.f;
            float v3 = acc2[mt][nt][3] + B21; v3 = v3 > 0.f ? v3 : 0.f;
            float o0 = u0 + v0, o1 = u1 + v1, o2 = u2 + v2, o3 = u3 + v3;
            *(float2*)&C[r0 * 128 + col] = make_float2(o0, o1);
            *(float2*)&C[r1 * 128 + col] = make_float2(o2, o3);
            s0 += o0 + o2; s1 += o1 + o3;
            q0 += o0 * o0 + o2 * o2; q1 += o1 * o1 + o3 * o3;
        }
#pragma unroll
        for (int m = 4; m <= 16; m <<= 1) {
            s0 += __shfl_xor_sync(0xffffffff, s0, m);
            s1 += __shfl_xor_sync(0xffffffff, s1, m);
            q0 += __shfl_xor_sync(0xffffffff, q0, m);
            q1 += __shfl_xor_sync(0xffffffff, q1, m);
        }
        if (frow == 0) {
            atomicAdd(&sumP[col], s0);
            atomicAdd(&sumP[col + 1], s1);
            atomicAdd(&sumsqP[col], q0);
            atomicAdd(&sumsqP[col + 1], q1);
        }
    }
}

// ============================================================================
// final BN normalize
// ============================================================================
__global__ void __launch_bounds__(256) k_bn_norm(const float* __restrict__ x,
                                                 float* __restrict__ out,
                                                 const float* __restrict__ gamma,
                                                 const float* __restrict__ beta,
                                                 const float* __restrict__ sumP,
                                                 const float* __restrict__ sumsqP) {
    int idx = blockIdx.x * blockDim.x + threadIdx.x;
    int base = idx * 4;
    if (base >= NN * DD) return;
    int c = base & 127;
    const float invN = 1.f / (float)NN;
    float4 v = *(const float4*)&x[base];
    float xv[4] = {v.x, v.y, v.z, v.w};
    float o[4];
#pragma unroll
    for (int j = 0; j < 4; j++) {
        float mu = sumP[c + j] * invN;
        float var = sumsqP[c + j] * invN - mu * mu;
        float rs = rsqrtf(var + EPS_BN);
        o[j] = gamma[c + j] * (xv[j] - mu) * rs + beta[c + j];
    }
    *(float4*)&out[base] = make_float4(o[0], o[1], o[2], o[3]);
}

// ============================================================================
extern "C" void kernel_launch(void* const* d_in, const int* in_sizes, int n_in,
                              void* d_out, int out_size) {
    const float* X     = (const float*)d_in[0];
    const int*   src   = (const int*)d_in[1];
    const int*   dst   = (const int*)d_in[2];
    const float* Winit = (const float*)d_in[3];
    const float* Wg    = (const float*)d_in[4];
    const float* bg    = (const float*)d_in[5];
    const float* Wr    = (const float*)d_in[6];
    const float* br    = (const float*)d_in[7];
    const float* gamma = (const float*)d_in[8];
    const float* beta  = (const float*)d_in[9];
    float* out = (float*)d_out;

    void *ph, *ptmp, *ps, *pq, *pwt, *pwth;
    cudaGetSymbolAddress(&ph, g_h);
    cudaGetSymbolAddress(&ptmp, g_tmp);
    cudaGetSymbolAddress(&ps, g_sum);
    cudaGetSymbolAddress(&pq, g_sumsq);
    cudaGetSymbolAddress(&pwt, g_Wt);
    cudaGetSymbolAddress(&pwth, g_Wth);
    float*  h    = (float*)ph;
    float*  tmp  = (float*)ptmp;
    float*  sum  = (float*)ps;
    float*  sumq = (float*)pq;
    float*  Wt   = (float*)pwt;
    __half* Wth  = (__half*)pwth;

    cudaFuncSetAttribute(k_layer_fused, cudaFuncAttributeMaxDynamicSharedMemorySize,
                         SMEM_FUSED);

    const int edgeGrid = EE / 256;
    const int nodeGrid = (NN + 255) / 256;
    const int gemmGrid = NN / 128;
    const int normGrid = (NN * DD / 4 + 255) / 256;

    k_zero<<<nodeGrid, 256>>>();                    // 0
    k_hist<<<edgeGrid, 256>>>(dst);                 // 1
    k_scan_lb<<<145, 512>>>();                      // 2
    k_fill<<<edgeGrid, 256>>>(src, dst);            // 3
    k_prep_w<<<6 * DD * DD / 256, 256>>>(Wg, Wr);   // 4
    k_init_tf32<<<gemmGrid, 256>>>(X, Winit);       // 5

    const float* layerIn[NLAYERS + 1] = {h, tmp, h, tmp};
    for (int l = 0; l < NLAYERS; l++) {
        const float* in = layerIn[l];
        float* outBuf = (float*)layerIn[l + 1];
        const float* sPrev = sum + (l - 1) * DD;
        const float* qPrev = sumq + (l - 1) * DD;
        const float* gPrev = gamma + (l - 1) * DD;
        const float* bPrev = beta + (l - 1) * DD;
        int useAff = (l > 0) ? 1 : 0;
        if (!useAff) { sPrev = sum; qPrev = sumq; gPrev = gamma; bPrev = beta; }
        k_layer_fused<<<gemmGrid, 256, SMEM_FUSED>>>(   // 6,7,8
            in, Wth + l * DD * DD, Wt + l * DD * DD,
            bg + l * DD, br + l * DD,
            sPrev, qPrev, gPrev, bPrev, useAff,
            outBuf, sum + l * DD, sumq + l * DD);
    }
    k_bn_norm<<<normGrid, 256>>>(tmp, out, gamma + 2 * DD, beta + 2 * DD,
                                 sum + 2 * DD, sumq + 2 * DD);               // 9
}

// round 11
// speedup vs baseline: 1.3569x; 1.3569x over previous
#include <cuda_runtime.h>
#include <cuda_fp16.h>
#include <cstdint>

#define NN 74240
#define EE 593920
#define DD 128
#define NLAYERS 3
#define EPS_BN 1e-5f

// ---------------- scratch ----------------
__device__ float g_h[NN * DD];
__device__ __half g_aggh[NN * DD];
__device__ float g_tmp[NN * DD];
__device__ float g_sum[NLAYERS * DD];
__device__ float g_sumsq[NLAYERS * DD];
__device__ __half g_Wth[NLAYERS * DD * DD];    // GraphConv W, fp16-rn, [l][n][k]
__device__ float g_Wt[NLAYERS * DD * DD];      // Residual W, tf32-rna, [l][n][k]
__device__ int g_deg[NN];
__device__ int g_off[NN + 1];
__device__ int g_pos[NN];
__device__ int g_csr[EE];
__device__ unsigned g_scanst[160];

// ---------------- helpers ----------------
__device__ __forceinline__ uint32_t smem_u32(const void* p) {
    uint32_t a;
    asm("{ .reg .u64 t; cvta.to.shared.u64 t, %1; cvt.u32.u64 %0, t; }" : "=r"(a) : "l"(p));
    return a;
}
__device__ __forceinline__ void cp16(uint32_t dst, const void* src) {
    asm volatile("cp.async.cg.shared.global [%0], [%1], 16;" :: "r"(dst), "l"(src));
}
#define CP_COMMIT() asm volatile("cp.async.commit_group;" ::: "memory")
#define CP_WAIT(n)  asm volatile("cp.async.wait_group %0;" :: "n"(n) : "memory")

__device__ __forceinline__ void ldsm_x4(uint32_t* r, uint32_t addr) {
    asm volatile("ldmatrix.sync.aligned.m8n8.x4.shared.b16 {%0,%1,%2,%3}, [%4];"
                 : "=r"(r[0]), "=r"(r[1]), "=r"(r[2]), "=r"(r[3]) : "r"(addr));
}
__device__ __forceinline__ void mma_tf32(float* c, const uint32_t* a, const uint32_t* b) {
    asm volatile(
        "mma.sync.aligned.m16n8k8.row.col.f32.tf32.tf32.f32 "
        "{%0,%1,%2,%3}, {%4,%5,%6,%7}, {%8,%9}, {%0,%1,%2,%3};"
        : "+f"(c[0]), "+f"(c[1]), "+f"(c[2]), "+f"(c[3])
        : "r"(a[0]), "r"(a[1]), "r"(a[2]), "r"(a[3]), "r"(b[0]), "r"(b[1]));
}
__device__ __forceinline__ void mma_f16(float* c, const uint32_t* a, const uint32_t* b) {
    asm volatile(
        "mma.sync.aligned.m16n8k16.row.col.f32.f16.f16.f32 "
        "{%0,%1,%2,%3}, {%4,%5,%6,%7}, {%8,%9}, {%0,%1,%2,%3};"
        : "+f"(c[0]), "+f"(c[1]), "+f"(c[2]), "+f"(c[3])
        : "r"(a[0]), "r"(a[1]), "r"(a[2]), "r"(a[3]), "r"(b[0]), "r"(b[1]));
}
__device__ __forceinline__ void split_tf32(float v, uint32_t& hi, uint32_t& lo) {
    asm("cvt.rna.tf32.f32 %0, %1;" : "=r"(hi) : "f"(v));
    float r = v - __uint_as_float(hi);
    asm("cvt.rna.tf32.f32 %0, %1;" : "=r"(lo) : "f"(r));
}

// ============================================================================
// zero + weight prep (merged; both trivially parallel, 384 blocks x 256)
// ============================================================================
__global__ void __launch_bounds__(256) k_zero_prep(const float* __restrict__ Wg,
                                                   const float* __restrict__ Wr) {
    int i = blockIdx.x * 256 + threadIdx.x;     // 0..98303
    if (i < NN) g_deg[i] = 0;
    if (i < NLAYERS * DD) { g_sum[i] = 0.f; g_sumsq[i] = 0.f; }
    if (i < 160) g_scanst[i] = 0u;
    // weight prep: exactly 98304 = 6 * 16384 elements
    int mat6 = i >> 14;
    int e = i & 16383;
    int n = e >> 7, k = e & 127;
    int l = mat6 >> 1, op = mat6 & 1;
    const float* src = (op ? Wr : Wg) + l * DD * DD;
    float v = src[k * 128 + n];
    if (op == 0) {
        g_Wth[l * 16384 + n * 128 + k] = __float2half_rn(v);
    } else {
        uint32_t u;
        asm("cvt.rna.tf32.f32 %0, %1;" : "=r"(u) : "f"(v));
        g_Wt[l * 16384 + n * 128 + k] = __uint_as_float(u);
    }
}

// ============================================================================
// hist + decoupled-lookback scan + fill
// ============================================================================
__global__ void __launch_bounds__(256) k_hist(const int* __restrict__ dst) {
    int e = blockIdx.x * 256 + threadIdx.x;
    if (e < EE) atomicAdd(&g_deg[dst[e]], 1);
}
__global__ void __launch_bounds__(512) k_scan_lb() {
    __shared__ int ws[16];
    __shared__ unsigned sprefix;
    int tid = threadIdx.x;
    int lane = tid & 31, w = tid >> 5;
    int gi = blockIdx.x * 512 + tid;
    int v = g_deg[gi];
    int x = v;
#pragma unroll
    for (int o = 1; o < 32; o <<= 1) {
        int t = __shfl_up_sync(0xffffffff, x, o);
        if (lane >= o) x += t;
    }
    if (lane == 31) ws[w] = x;
    __syncthreads();
    if (w == 0) {
        int y = (lane < 16) ? ws[lane] : 0;
#pragma unroll
        for (int o = 1; o < 16; o <<= 1) {
            int t = __shfl_up_sync(0xffffffff, y, o);
            if (lane >= o) y += t;
        }
        if (lane < 16) ws[lane] = y;
    }
    __syncthreads();
    int base = (w > 0) ? ws[w - 1] : 0;
    int excl = base + x - v;
    int btot = ws[15];
    if (tid == 0) {
        unsigned pub = ((blockIdx.x == 0 ? 2u : 1u) << 30) | (unsigned)btot;
        atomicExch(&g_scanst[blockIdx.x], pub);
        unsigned pre = 0;
        if (blockIdx.x > 0) {
            int i = blockIdx.x - 1;
            while (true) {
                unsigned s;
                do { s = atomicAdd(&g_scanst[i], 0u); } while (s == 0u);
                pre += s & 0x3FFFFFFFu;
                if ((s >> 30) == 2u) break;
                i--;
            }
            atomicExch(&g_scanst[blockIdx.x], (2u << 30) | (pre + (unsigned)btot));
        }
        sprefix = pre;
    }
    __syncthreads();
    int off = (int)sprefix + excl;
    g_off[gi] = off;
    g_pos[gi] = off;
    if (gi == 0) g_off[NN] = EE;
}
__global__ void __launch_bounds__(256) k_fill(const int* __restrict__ src,
                                              const int* __restrict__ dst) {
    int e = blockIdx.x * 256 + threadIdx.x;
    if (e < EE) {
        int p = atomicAdd(&g_pos[dst[e]], 1);
        g_csr[p] = src[e];
    }
}

// ============================================================================
// gather (R7-exact): aggh[d] = fp16( s * sum in[src] + deg * t )
// ============================================================================
__global__ void __launch_bounds__(256) k_gather(const float* __restrict__ in,
                                                const float* __restrict__ sumP,
                                                const float* __restrict__ sumsqP,
                                                const float* __restrict__ gamma,
                                                const float* __restrict__ beta,
                                                int useAff) {
    __shared__ float2 aff[128];
    int tid = threadIdx.x;
    if (tid < 128) {
        float2 a = make_float2(1.f, 0.f);
        if (useAff) {
            const float invN = 1.f / (float)NN;
            float mu = sumP[tid] * invN;
            float var = sumsqP[tid] * invN - mu * mu;
            float s = gamma[tid] * rsqrtf(var + EPS_BN);
            a = make_float2(s, beta[tid] - mu * s);
        }
        aff[tid] = a;
    }
    __syncthreads();

    int gid = blockIdx.x * 256 + tid;
    int node = gid >> 5, lane = gid & 31;
    if (node >= NN) return;
    int beg = g_off[node], end = g_off[node + 1];
    float4 acc0 = make_float4(0.f, 0.f, 0.f, 0.f);
    float4 acc1 = make_float4(0.f, 0.f, 0.f, 0.f);
    float4 acc2 = make_float4(0.f, 0.f, 0.f, 0.f);
    float4 acc3 = make_float4(0.f, 0.f, 0.f, 0.f);
    int lo4 = lane * 4;
    for (int base = beg; base < end; base += 32) {
        int i = base + lane;
        int idx = (i < end) ? __ldg(&g_csr[i]) : 0;
        int cnt = min(32, end - base);
        int j = 0;
        for (; j + 4 <= cnt; j += 4) {
            int s0 = __shfl_sync(0xffffffff, idx, j);
            int s1 = __shfl_sync(0xffffffff, idx, j + 1);
            int s2 = __shfl_sync(0xffffffff, idx, j + 2);
            int s3 = __shfl_sync(0xffffffff, idx, j + 3);
            float4 v0 = *(const float4*)&in[s0 * 128 + lo4];
            float4 v1 = *(const float4*)&in[s1 * 128 + lo4];
            float4 v2 = *(const float4*)&in[s2 * 128 + lo4];
            float4 v3 = *(const float4*)&in[s3 * 128 + lo4];
            acc0.x += v0.x; acc0.y += v0.y; acc0.z += v0.z; acc0.w += v0.w;
            acc1.x += v1.x; acc1.y += v1.y; acc1.z += v1.z; acc1.w += v1.w;
            acc2.x += v2.x; acc2.y += v2.y; acc2.z += v2.z; acc2.w += v2.w;
            acc3.x += v3.x; acc3.y += v3.y; acc3.z += v3.z; acc3.w += v3.w;
        }
        for (; j < cnt; j++) {
            int s = __shfl_sync(0xffffffff, idx, j);
            float4 v = *(const float4*)&in[s * 128 + lo4];
            acc0.x += v.x; acc0.y += v.y; acc0.z += v.z; acc0.w += v.w;
        }
    }
    acc0.x += acc1.x + acc2.x + acc3.x;
    acc0.y += acc1.y + acc2.y + acc3.y;
    acc0.z += acc1.z + acc2.z + acc3.z;
    acc0.w += acc1.w + acc2.w + acc3.w;
    float deg = (float)(end - beg);
    float2 a0 = aff[lo4], a1 = aff[lo4 + 1], a2 = aff[lo4 + 2], a3 = aff[lo4 + 3];
    float o0 = a0.x * acc0.x + deg * a0.y;
    float o1 = a1.x * acc0.y + deg * a1.y;
    float o2 = a2.x * acc0.z + deg * a2.y;
    float o3 = a3.x * acc0.w + deg * a3.y;
    __half2 p0 = __floats2half2_rn(o0, o1);
    __half2 p1 = __floats2half2_rn(o2, o3);
    uint2 pk;
    pk.x = *(uint32_t*)&p0;
    pk.y = *(uint32_t*)&p1;
    *(uint2*)&g_aggh[node * 128 + lo4] = pk;
}

// ============================================================================
// init GEMM, split-tf32 (3-term compensation; ~fp32): g_h = X[NN,75] @ W[75,128]
// ============================================================================
#define IXS 44
#define IWS 132
__global__ void __launch_bounds__(256) k_init_tf32(const float* __restrict__ X,
                                                   const float* __restrict__ W) {
    __shared__ float Xs[128 * IXS];
    __shared__ float Ws[40 * IWS];
    int tid = threadIdx.x;
    int lane = tid & 31;
    int wid = tid >> 5;
    int mwarp = wid & 3, nwarp = wid >> 2;
    int rowBase = blockIdx.x * 128;
    int mBase = mwarp * 32, nBase = nwarp * 64;
    int frow = lane >> 2, fcol = lane & 3;

    float acc[2][8][4];
#pragma unroll
    for (int mt = 0; mt < 2; mt++)
#pragma unroll
        for (int nt = 0; nt < 8; nt++)
#pragma unroll
            for (int j = 0; j < 4; j++) acc[mt][nt][j] = 0.f;

    for (int k0 = 0; k0 < 80; k0 += 40) {
        for (int idx = tid; idx < 128 * 40; idx += 256) {
            int r = idx / 40, k = idx - r * 40;
            int gk = k0 + k;
            Xs[r * IXS + k] = (gk < 75) ? X[(rowBase + r) * 75 + gk] : 0.f;
        }
        for (int idx = tid; idx < 40 * 128; idx += 256) {
            int k = idx >> 7, n = idx & 127;
            int gk = k0 + k;
            Ws[k * IWS + n] = (gk < 75) ? W[gk * 128 + n] : 0.f;
        }
        __syncthreads();
#pragma unroll
        for (int kb = 0; kb < 40; kb += 8) {
            uint32_t ahi[2][4], alo[2][4];
#pragma unroll
            for (int mt = 0; mt < 2; mt++) {
                int r0 = mBase + mt * 16 + frow;
                split_tf32(Xs[r0 * IXS + kb + fcol],           ahi[mt][0], alo[mt][0]);
                split_tf32(Xs[(r0 + 8) * IXS + kb + fcol],     ahi[mt][1], alo[mt][1]);
                split_tf32(Xs[r0 * IXS + kb + fcol + 4],       ahi[mt][2], alo[mt][2]);
                split_tf32(Xs[(r0 + 8) * IXS + kb + fcol + 4], ahi[mt][3], alo[mt][3]);
            }
            uint32_t bhi[8][2], blo[8][2];
#pragma unroll
            for (int nt = 0; nt < 8; nt++) {
                int n = nBase + nt * 8 + frow;
                split_tf32(Ws[(kb + fcol) * IWS + n],     bhi[nt][0], blo[nt][0]);
                split_tf32(Ws[(kb + fcol + 4) * IWS + n], bhi[nt][1], blo[nt][1]);
            }
#pragma unroll
            for (int mt = 0; mt < 2; mt++)
#pragma unroll
                for (int nt = 0; nt < 8; nt++) {
                    mma_tf32(acc[mt][nt], ahi[mt], bhi[nt]);
                    mma_tf32(acc[mt][nt], alo[mt], bhi[nt]);
                    mma_tf32(acc[mt][nt], ahi[mt], blo[nt]);
                }
        }
        __syncthreads();
    }
#pragma unroll
    for (int mt = 0; mt < 2; mt++)
#pragma unroll
        for (int nt = 0; nt < 8; nt++) {
            int col = nBase + nt * 8 + fcol * 2;
            int r0 = rowBase + mBase + mt * 16 + frow;
            *(float2*)&g_h[r0 * 128 + col]       = make_float2(acc[mt][nt][0], acc[mt][nt][1]);
            *(float2*)&g_h[(r0 + 8) * 128 + col] = make_float2(acc[mt][nt][2], acc[mt][nt][3]);
        }
}

// ============================================================================
// Fused layer GEMM, N-SPLIT for occupancy 2:
//   CTA computes rows [rowBase, rowBase+128) x cols [colBase, colBase+64).
//   C = relu(A1h @ W1h + b1) + relu( (s*A2 + t) @ W2 + b2 )  + BN stats
// GC branch fp16 m16n8k16; RES branch tf32 m16n8k8.
// Stage: A1h 128x80B | W1h 64x80B | A2 128x144B | W2 64x144B = 43008 B
// ============================================================================
#define FA1_B   0
#define FW1_B   10240
#define FA2_B   15360
#define FW2_B   33792
#define FSTG_B  43008
#define FBIAS1  (2 * FSTG_B / 4)      // float idx 21504
#define FBIAS2  (FBIAS1 + 64)
#define FAFF    (FBIAS2 + 64)         // 128 float2
#define SMEM_FUSED (2 * FSTG_B + 256 + 256 + 1024)

__device__ __forceinline__ void f_issue(uint32_t sb, int st, int c, int tid, int rowBase,
                                        const __half* A1h, const float* A2,
                                        const __half* W1p, const float* W2p) {
    uint32_t stb = sb + st * FSTG_B;
    int k0 = c * 32;
#pragma unroll
    for (int i = 0; i < 2; i++) {               // A1h: 512 cp16
        int idx = i * 256 + tid;
        int r = idx >> 2, q = idx & 3;
        cp16(stb + FA1_B + r * 80 + q * 16, A1h + (rowBase + r) * 128 + k0 + q * 8);
    }
    {                                           // W1h: 256 cp16
        int r = tid >> 2, q = tid & 3;
        cp16(stb + FW1_B + r * 80 + q * 16, W1p + r * 128 + k0 + q * 8);
    }
#pragma unroll
    for (int i = 0; i < 4; i++) {               // A2: 1024 cp16
        int idx = i * 256 + tid;
        int r = idx >> 3, q = idx & 7;
        cp16(stb + FA2_B + r * 144 + q * 16, A2 + (rowBase + r) * 128 + k0 + q * 4);
    }
#pragma unroll
    for (int i = 0; i < 2; i++) {               // W2: 512 cp16
        int idx = i * 256 + tid;
        int r = idx >> 3, q = idx & 7;
        cp16(stb + FW2_B + r * 144 + q * 16, W2p + r * 128 + k0 + q * 4);
    }
    CP_COMMIT();
}

__device__ __forceinline__ void f_compute(uint32_t sb, int st, int k0,
                                          int mBase, int nBase, int lane,
                                          const float2* affS,
                                          float acc1[2][4][4], float acc2[2][4][4]) {
    uint32_t stb = sb + st * FSTG_B;
    int g = lane >> 3, lr = lane & 7;
    int fcol = lane & 3;
    int arow = ((g & 1) << 3) + lr;
    int abyte = (g >> 1) << 4;
    int brow = ((g >> 1) << 3) + lr;
    int bbyte = (g & 1) << 4;

    // ---- GC: fp16 k16 ----
#pragma unroll
    for (int kb = 0; kb < 32; kb += 16) {
        uint32_t a1[2][4];
#pragma unroll
        for (int mt = 0; mt < 2; mt++) {
            uint32_t base = stb + FA1_B + (uint32_t)(mBase + mt * 16 + arow) * 80 + kb * 2 + abyte;
            ldsm_x4(a1[mt], base);
        }
        uint32_t bf[2][4];
#pragma unroll
        for (int p = 0; p < 2; p++) {
            uint32_t base = stb + FW1_B + (uint32_t)(nBase + p * 16 + brow) * 80 + kb * 2 + bbyte;
            ldsm_x4(bf[p], base);
        }
#pragma unroll
        for (int mt = 0; mt < 2; mt++)
#pragma unroll
            for (int p = 0; p < 2; p++) {
                mma_f16(acc1[mt][2 * p],     a1[mt], &bf[p][0]);
                mma_f16(acc1[mt][2 * p + 1], a1[mt], &bf[p][2]);
            }
    }

    // ---- RES: tf32 k8, affine on A2 fragments ----
#pragma unroll
    for (int kb = 0; kb < 32; kb += 8) {
        uint32_t a2[2][4];
#pragma unroll
        for (int mt = 0; mt < 2; mt++) {
            uint32_t base = stb + FA2_B + (uint32_t)(mBase + mt * 16 + arow) * 144 + kb * 4 + abyte;
            ldsm_x4(a2[mt], base);
        }
        float2 f0 = affS[k0 + kb + fcol];
        float2 f4 = affS[k0 + kb + fcol + 4];
#pragma unroll
        for (int mt = 0; mt < 2; mt++) {
            a2[mt][0] = __float_as_uint(fmaf(f0.x, __uint_as_float(a2[mt][0]), f0.y));
            a2[mt][1] = __float_as_uint(fmaf(f0.x, __uint_as_float(a2[mt][1]), f0.y));
            a2[mt][2] = __float_as_uint(fmaf(f4.x, __uint_as_float(a2[mt][2]), f4.y));
            a2[mt][3] = __float_as_uint(fmaf(f4.x, __uint_as_float(a2[mt][3]), f4.y));
        }
        uint32_t b2[2][4];
#pragma unroll
        for (int p = 0; p < 2; p++) {
            uint32_t base = stb + FW2_B + (uint32_t)(nBase + p * 16 + brow) * 144 + kb * 4 + bbyte;
            ldsm_x4(b2[p], base);
        }
#pragma unroll
        for (int mt = 0; mt < 2; mt++)
#pragma unroll
            for (int p = 0; p < 2; p++) {
                mma_tf32(acc2[mt][2 * p],     a2[mt], &b2[p][0]);
                mma_tf32(acc2[mt][2 * p + 1], a2[mt], &b2[p][2]);
            }
    }
}

__global__ void __launch_bounds__(256, 2) k_layer_fused(
    const __half* __restrict__ A1h, const float* __restrict__ A2,
    const __half* __restrict__ W1h, const float* __restrict__ W2t,
    const float* __restrict__ b1, const float* __restrict__ b2,
    const float* __restrict__ sumPrev, const float* __restrict__ sumsqPrev,
    const float* __restrict__ gammaPrev, const float* __restrict__ betaPrev, int useAff,
    float* __restrict__ C, float* __restrict__ sumP, float* __restrict__ sumsqP) {
    extern __shared__ char smc[];
    float* smf = (float*)smc;
    uint32_t sb = smem_u32(smc);
    int tid = threadIdx.x;
    int lane = tid & 31;
    int wid = tid >> 5;
    int mwarp = wid & 3, nwarp = wid >> 2;
    int rowBase = (blockIdx.x >> 1) * 128;
    int colBase = (blockIdx.x & 1) * 64;
    int mBase = mwarp * 32, nBase = nwarp * 32;
    int frow = lane >> 2, fcol = lane & 3;

    const __half* W1p = W1h + colBase * 128;
    const float*  W2p = W2t + colBase * 128;

    if (tid < 64) {
        smf[FBIAS1 + tid] = b1[colBase + tid];
        smf[FBIAS2 + tid] = b2[colBase + tid];
    }
    if (tid < 128) {
        float2 a = make_float2(1.f, 0.f);
        if (useAff) {
            const float invN = 1.f / (float)NN;
            float mu = sumPrev[tid] * invN;
            float var = sumsqPrev[tid] * invN - mu * mu;
            float s = gammaPrev[tid] * rsqrtf(var + EPS_BN);
            a = make_float2(s, betaPrev[tid] - mu * s);
        }
        ((float2*)(smf + FAFF))[tid] = a;
    }
    const float2* affS = (const float2*)(smf + FAFF);

    float acc1[2][4][4], acc2[2][4][4];
#pragma unroll
    for (int mt = 0; mt < 2; mt++)
#pragma unroll
        for (int nt = 0; nt < 4; nt++)
#pragma unroll
            for (int j = 0; j < 4; j++) { acc1[mt][nt][j] = 0.f; acc2[mt][nt][j] = 0.f; }

    f_issue(sb, 0, 0, tid, rowBase, A1h, A2, W1p, W2p);
    f_issue(sb, 1, 1, tid, rowBase, A1h, A2, W1p, W2p);

    CP_WAIT(1); __syncthreads();
    f_compute(sb, 0, 0, mBase, nBase, lane, affS, acc1, acc2);
    __syncthreads();
    f_issue(sb, 0, 2, tid, rowBase, A1h, A2, W1p, W2p);

    CP_WAIT(1); __syncthreads();
    f_compute(sb, 1, 32, mBase, nBase, lane, affS, acc1, acc2);
    __syncthreads();
    f_issue(sb, 1, 3, tid, rowBase, A1h, A2, W1p, W2p);

    CP_WAIT(1); __syncthreads();
    f_compute(sb, 0, 64, mBase, nBase, lane, affS, acc1, acc2);
    __syncthreads();

    CP_WAIT(0); __syncthreads();
    f_compute(sb, 1, 96, mBase, nBase, lane, affS, acc1, acc2);

    // epilogue
    const float* bs1 = smf + FBIAS1;
    const float* bs2 = smf + FBIAS2;
#pragma unroll
    for (int nt = 0; nt < 4; nt++) {
        int lcol = nBase + nt * 8 + fcol * 2;        // 0..63
        int gcol = colBase + lcol;
        float B10 = bs1[lcol], B11 = bs1[lcol + 1];
        float B20 = bs2[lcol], B21 = bs2[lcol + 1];
        float s0 = 0.f, s1 = 0.f, q0 = 0.f, q1 = 0.f;
#pragma unroll
        for (int mt = 0; mt < 2; mt++) {
            int r0 = rowBase + mBase + mt * 16 + frow;
            int r1 = r0 + 8;
            float u0 = acc1[mt][nt][0] + B10; u0 = u0 > 0.f ? u0 : 0.f;
            float u1 = acc1[mt][nt][1] + B11; u1 = u1 > 0.f ? u1 : 0.f;
            float u2 = acc1[mt][nt][2] + B10; u2 = u2 > 0.f ? u2 : 0.f;
            float u3 = acc1[mt][nt][3] + B11; u3 = u3 > 0.f ? u3 : 0.f;
            float v0 = acc2[mt][nt][0] + B20; v0 = v0 > 0.f ? v0 : 0.f;
            float v1 = acc2[mt][nt][1] + B21; v1 = v1 > 0.f ? v1 : 0.f;
            float v2 = acc2[mt][nt][2] + B20; v2 = v2 > 0.f ? v2 : 0.f;
            float v3 = acc2[mt][nt][3] + B21; v3 = v3 > 0.f ? v3 : 0.f;
            float o0 = u0 + v0, o1 = u1 + v1, o2 = u2 + v2, o3 = u3 + v3;
            *(float2*)&C[r0 * 128 + gcol] = make_float2(o0, o1);
            *(float2*)&C[r1 * 128 + gcol] = make_float2(o2, o3);
            s0 += o0 + o2; s1 += o1 + o3;
            q0 += o0 * o0 + o2 * o2; q1 += o1 * o1 + o3 * o3;
        }
#pragma unroll
        for (int m = 4; m <= 16; m <<= 1) {
            s0 += __shfl_xor_sync(0xffffffff, s0, m);
            s1 += __shfl_xor_sync(0xffffffff, s1, m);
            q0 += __shfl_xor_sync(0xffffffff, q0, m);
            q1 += __shfl_xor_sync(0xffffffff, q1, m);
        }
        if (frow == 0) {
            atomicAdd(&sumP[gcol], s0);
            atomicAdd(&sumP[gcol + 1], s1);
            atomicAdd(&sumsqP[gcol], q0);
            atomicAdd(&sumsqP[gcol + 1], q1);
        }
    }
}

// ============================================================================
// final BN normalize
// ============================================================================
__global__ void __launch_bounds__(256) k_bn_norm(const float* __restrict__ x,
                                                 float* __restrict__ out,
                                                 const float* __restrict__ gamma,
                                                 const float* __restrict__ beta,
                                                 const float* __restrict__ sumP,
                                                 const float* __restrict__ sumsqP) {
    int idx = blockIdx.x * blockDim.x + threadIdx.x;
    int base = idx * 4;
    if (base >= NN * DD) return;
    int c = base & 127;
    const float invN = 1.f / (float)NN;
    float4 v = *(const float4*)&x[base];
    float xv[4] = {v.x, v.y, v.z, v.w};
    float o[4];
#pragma unroll
    for (int j = 0; j < 4; j++) {
        float mu = sumP[c + j] * invN;
        float var = sumsqP[c + j] * invN - mu * mu;
        float rs = rsqrtf(var + EPS_BN);
        o[j] = gamma[c + j] * (xv[j] - mu) * rs + beta[c + j];
    }
    *(float4*)&out[base] = make_float4(o[0], o[1], o[2], o[3]);
}

// ============================================================================
extern "C" void kernel_launch(void* const* d_in, const int* in_sizes, int n_in,
                              void* d_out, int out_size) {
    const float* X     = (const float*)d_in[0];
    const int*   src   = (const int*)d_in[1];
    const int*   dst   = (const int*)d_in[2];
    const float* Winit = (const float*)d_in[3];
    const float* Wg    = (const float*)d_in[4];
    const float* bg    = (const float*)d_in[5];
    const float* Wr    = (const float*)d_in[6];
    const float* br    = (const float*)d_in[7];
    const float* gamma = (const float*)d_in[8];
    const float* beta  = (const float*)d_in[9];
    float* out = (float*)d_out;

    void *ph, *pagg, *ptmp, *ps, *pq, *pwt, *pwth;
    cudaGetSymbolAddress(&ph, g_h);
    cudaGetSymbolAddress(&pagg, g_aggh);
    cudaGetSymbolAddress(&ptmp, g_tmp);
    cudaGetSymbolAddress(&ps, g_sum);
    cudaGetSymbolAddress(&pq, g_sumsq);
    cudaGetSymbolAddress(&pwt, g_Wt);
    cudaGetSymbolAddress(&pwth, g_Wth);
    float*  h    = (float*)ph;
    __half* aggh = (__half*)pagg;
    float*  tmp  = (float*)ptmp;
    float*  sum  = (float*)ps;
    float*  sumq = (float*)pq;
    float*  Wt   = (float*)pwt;
    __half* Wth  = (__half*)pwth;

    cudaFuncSetAttribute(k_layer_fused, cudaFuncAttributeMaxDynamicSharedMemorySize,
                         SMEM_FUSED);

    const int edgeGrid = EE / 256;           // 2320
    const int warpGrid = (NN * 32) / 256;    // 9280
    const int gemmGrid = NN / 128;           // 580
    const int fusedGrid = gemmGrid * 2;      // 1160
    const int normGrid = (NN * DD / 4 + 255) / 256;

    k_zero_prep<<<384, 256>>>(Wg, Wr);                // 0
    k_hist<<<edgeGrid, 256>>>(dst);                   // 1
    k_scan_lb<<<145, 512>>>();                        // 2
    k_fill<<<edgeGrid, 256>>>(src, dst);              // 3
    k_init_tf32<<<gemmGrid, 256>>>(X, Winit);         // 4

    const float* layerIn[NLAYERS + 1] = {h, tmp, h, tmp};
    for (int l = 0; l < NLAYERS; l++) {
        const float* in = layerIn[l];
        float* outBuf = (float*)layerIn[l + 1];
        const float* sPrev = sum + (l - 1) * DD;
        const float* qPrev = sumq + (l - 1) * DD;
        const float* gPrev = gamma + (l - 1) * DD;
        const float* bPrev = beta + (l - 1) * DD;
        int useAff = (l > 0) ? 1 : 0;
        if (!useAff) { sPrev = sum; qPrev = sumq; gPrev = gamma; bPrev = beta; }
        k_gather<<<warpGrid, 256>>>(in, sPrev, qPrev, gPrev, bPrev, useAff);   // 5,7,9
        k_layer_fused<<<fusedGrid, 256, SMEM_FUSED>>>(                         // 6,8,10
            aggh, in, Wth + l * DD * DD, Wt + l * DD * DD,
            bg + l * DD, br + l * DD,
            sPrev, qPrev, gPrev, bPrev, useAff,
            outBuf, sum + l * DD, sumq + l * DD);
    }
    k_bn_norm<<<normGrid, 256>>>(tmp, out, gamma + 2 * DD, beta + 2 * DD,
                                 sum + 2 * DD, sumq + 2 * DD);                 // 11
}

// round 12
// speedup vs baseline: 1.4631x; 1.0783x over previous
#include <cuda_runtime.h>
#include <cuda_fp16.h>
#include <cstdint>

#define NN 74240
#define EE 593920
#define DD 128
#define NLAYERS 3
#define EPS_BN 1e-5f

// ---------------- scratch ----------------
__device__ __half g_hA[NN * DD];               // fp16 activations (ping)
__device__ __half g_hB[NN * DD];               // fp16 activations (pong)
__device__ __half g_aggh[NN * DD];             // fp16 aggregate
__device__ float g_tmp[NN * DD];               // final-layer fp32 pre-BN
__device__ float g_sum[NLAYERS * DD];
__device__ float g_sumsq[NLAYERS * DD];
__device__ __half g_Wth[NLAYERS * 2 * DD * DD]; // both weights fp16-rn, [l][op][n][k]
__device__ int g_deg[NN];
__device__ int g_off[NN + 1];
__device__ int g_pos[NN];
__device__ int g_csr[EE];
__device__ unsigned g_scanst[160];

// ---------------- helpers ----------------
__device__ __forceinline__ uint32_t smem_u32(const void* p) {
    uint32_t a;
    asm("{ .reg .u64 t; cvta.to.shared.u64 t, %1; cvt.u32.u64 %0, t; }" : "=r"(a) : "l"(p));
    return a;
}
__device__ __forceinline__ void cp16(uint32_t dst, const void* src) {
    asm volatile("cp.async.cg.shared.global [%0], [%1], 16;" :: "r"(dst), "l"(src));
}
#define CP_COMMIT() asm volatile("cp.async.commit_group;" ::: "memory")
#define CP_WAIT(n)  asm volatile("cp.async.wait_group %0;" :: "n"(n) : "memory")

__device__ __forceinline__ void ldsm_x4(uint32_t* r, uint32_t addr) {
    asm volatile("ldmatrix.sync.aligned.m8n8.x4.shared.b16 {%0,%1,%2,%3}, [%4];"
                 : "=r"(r[0]), "=r"(r[1]), "=r"(r[2]), "=r"(r[3]) : "r"(addr));
}
__device__ __forceinline__ void mma_tf32(float* c, const uint32_t* a, const uint32_t* b) {
    asm volatile(
        "mma.sync.aligned.m16n8k8.row.col.f32.tf32.tf32.f32 "
        "{%0,%1,%2,%3}, {%4,%5,%6,%7}, {%8,%9}, {%0,%1,%2,%3};"
        : "+f"(c[0]), "+f"(c[1]), "+f"(c[2]), "+f"(c[3])
        : "r"(a[0]), "r"(a[1]), "r"(a[2]), "r"(a[3]), "r"(b[0]), "r"(b[1]));
}
__device__ __forceinline__ void mma_f16(float* c, const uint32_t* a, const uint32_t* b) {
    asm volatile(
        "mma.sync.aligned.m16n8k16.row.col.f32.f16.f16.f32 "
        "{%0,%1,%2,%3}, {%4,%5,%6,%7}, {%8,%9}, {%0,%1,%2,%3};"
        : "+f"(c[0]), "+f"(c[1]), "+f"(c[2]), "+f"(c[3])
        : "r"(a[0]), "r"(a[1]), "r"(a[2]), "r"(a[3]), "r"(b[0]), "r"(b[1]));
}
__device__ __forceinline__ void split_tf32(float v, uint32_t& hi, uint32_t& lo) {
    asm("cvt.rna.tf32.f32 %0, %1;" : "=r"(hi) : "f"(v));
    float r = v - __uint_as_float(hi);
    asm("cvt.rna.tf32.f32 %0, %1;" : "=r"(lo) : "f"(r));
}
__device__ __forceinline__ uint32_t packh2(float a, float b) {
    __half2 h = __floats2half2_rn(a, b);
    return *(uint32_t*)&h;
}

// ============================================================================
// zero + weight prep (384 blocks x 256)
// ============================================================================
__global__ void __launch_bounds__(256) k_zero_prep(const float* __restrict__ Wg,
                                                   const float* __restrict__ Wr) {
    int i = blockIdx.x * 256 + threadIdx.x;     // 0..98303
    if (i < NN) g_deg[i] = 0;
    if (i < NLAYERS * DD) { g_sum[i] = 0.f; g_sumsq[i] = 0.f; }
    if (i < 160) g_scanst[i] = 0u;
    int mat6 = i >> 14;
    int e = i & 16383;
    int n = e >> 7, k = e & 127;
    int l = mat6 >> 1, op = mat6 & 1;
    const float* src = (op ? Wr : Wg) + l * DD * DD;
    g_Wth[(l * 2 + op) * 16384 + n * 128 + k] = __float2half_rn(src[k * 128 + n]);
}

// ============================================================================
// hist + decoupled-lookback scan + fill
// ============================================================================
__global__ void __launch_bounds__(256) k_hist(const int* __restrict__ dst) {
    int e = blockIdx.x * 256 + threadIdx.x;
    if (e < EE) atomicAdd(&g_deg[dst[e]], 1);
}
__global__ void __launch_bounds__(512) k_scan_lb() {
    __shared__ int ws[16];
    __shared__ unsigned sprefix;
    int tid = threadIdx.x;
    int lane = tid & 31, w = tid >> 5;
    int gi = blockIdx.x * 512 + tid;
    int v = g_deg[gi];
    int x = v;
#pragma unroll
    for (int o = 1; o < 32; o <<= 1) {
        int t = __shfl_up_sync(0xffffffff, x, o);
        if (lane >= o) x += t;
    }
    if (lane == 31) ws[w] = x;
    __syncthreads();
    if (w == 0) {
        int y = (lane < 16) ? ws[lane] : 0;
#pragma unroll
        for (int o = 1; o < 16; o <<= 1) {
            int t = __shfl_up_sync(0xffffffff, y, o);
            if (lane >= o) y += t;
        }
        if (lane < 16) ws[lane] = y;
    }
    __syncthreads();
    int base = (w > 0) ? ws[w - 1] : 0;
    int excl = base + x - v;
    int btot = ws[15];
    if (tid == 0) {
        unsigned pub = ((blockIdx.x == 0 ? 2u : 1u) << 30) | (unsigned)btot;
        atomicExch(&g_scanst[blockIdx.x], pub);
        unsigned pre = 0;
        if (blockIdx.x > 0) {
            int i = blockIdx.x - 1;
            while (true) {
                unsigned s;
                do { s = atomicAdd(&g_scanst[i], 0u); } while (s == 0u);
                pre += s & 0x3FFFFFFFu;
                if ((s >> 30) == 2u) break;
                i--;
            }
            atomicExch(&g_scanst[blockIdx.x], (2u << 30) | (pre + (unsigned)btot));
        }
        sprefix = pre;
    }
    __syncthreads();
    int off = (int)sprefix + excl;
    g_off[gi] = off;
    g_pos[gi] = off;
    if (gi == 0) g_off[NN] = EE;
}
__global__ void __launch_bounds__(256) k_fill(const int* __restrict__ src,
                                              const int* __restrict__ dst) {
    int e = blockIdx.x * 256 + threadIdx.x;
    if (e < EE) {
        int p = atomicAdd(&g_pos[dst[e]], 1);
        g_csr[p] = src[e];
    }
}

// ============================================================================
// gather (fp16 in / fp16 out): aggh[d] = fp16( s * sum in[src] + deg * t )
// ============================================================================
__global__ void __launch_bounds__(256) k_gather(const __half* __restrict__ in,
                                                const float* __restrict__ sumP,
                                                const float* __restrict__ sumsqP,
                                                const float* __restrict__ gamma,
                                                const float* __restrict__ beta,
                                                int useAff) {
    __shared__ float2 aff[128];
    int tid = threadIdx.x;
    if (tid < 128) {
        float2 a = make_float2(1.f, 0.f);
        if (useAff) {
            const float invN = 1.f / (float)NN;
            float mu = sumP[tid] * invN;
            float var = sumsqP[tid] * invN - mu * mu;
            float s = gamma[tid] * rsqrtf(var + EPS_BN);
            a = make_float2(s, beta[tid] - mu * s);
        }
        aff[tid] = a;
    }
    __syncthreads();

    int gid = blockIdx.x * 256 + tid;
    int node = gid >> 5, lane = gid & 31;
    if (node >= NN) return;
    int beg = g_off[node], end = g_off[node + 1];
    float4 acc0 = make_float4(0.f, 0.f, 0.f, 0.f);
    float4 acc1 = make_float4(0.f, 0.f, 0.f, 0.f);
    float4 acc2 = make_float4(0.f, 0.f, 0.f, 0.f);
    float4 acc3 = make_float4(0.f, 0.f, 0.f, 0.f);
    int lo4 = lane * 4;
    for (int base = beg; base < end; base += 32) {
        int i = base + lane;
        int idx = (i < end) ? __ldg(&g_csr[i]) : 0;
        int cnt = min(32, end - base);
        int j = 0;
        for (; j + 4 <= cnt; j += 4) {
            int s0 = __shfl_sync(0xffffffff, idx, j);
            int s1 = __shfl_sync(0xffffffff, idx, j + 1);
            int s2 = __shfl_sync(0xffffffff, idx, j + 2);
            int s3 = __shfl_sync(0xffffffff, idx, j + 3);
            uint2 u0 = *(const uint2*)&in[s0 * 128 + lo4];
            uint2 u1 = *(const uint2*)&in[s1 * 128 + lo4];
            uint2 u2 = *(const uint2*)&in[s2 * 128 + lo4];
            uint2 u3 = *(const uint2*)&in[s3 * 128 + lo4];
            float2 f;
            f = __half22float2(*(__half2*)&u0.x); acc0.x += f.x; acc0.y += f.y;
            f = __half22float2(*(__half2*)&u0.y); acc0.z += f.x; acc0.w += f.y;
            f = __half22float2(*(__half2*)&u1.x); acc1.x += f.x; acc1.y += f.y;
            f = __half22float2(*(__half2*)&u1.y); acc1.z += f.x; acc1.w += f.y;
            f = __half22float2(*(__half2*)&u2.x); acc2.x += f.x; acc2.y += f.y;
            f = __half22float2(*(__half2*)&u2.y); acc2.z += f.x; acc2.w += f.y;
            f = __half22float2(*(__half2*)&u3.x); acc3.x += f.x; acc3.y += f.y;
            f = __half22float2(*(__half2*)&u3.y); acc3.z += f.x; acc3.w += f.y;
        }
        for (; j < cnt; j++) {
            int s = __shfl_sync(0xffffffff, idx, j);
            uint2 u = *(const uint2*)&in[s * 128 + lo4];
            float2 f;
            f = __half22float2(*(__half2*)&u.x); acc0.x += f.x; acc0.y += f.y;
            f = __half22float2(*(__half2*)&u.y); acc0.z += f.x; acc0.w += f.y;
        }
    }
    acc0.x += acc1.x + acc2.x + acc3.x;
    acc0.y += acc1.y + acc2.y + acc3.y;
    acc0.z += acc1.z + acc2.z + acc3.z;
    acc0.w += acc1.w + acc2.w + acc3.w;
    float deg = (float)(end - beg);
    float2 a0 = aff[lo4], a1 = aff[lo4 + 1], a2 = aff[lo4 + 2], a3 = aff[lo4 + 3];
    uint2 pk;
    pk.x = packh2(a0.x * acc0.x + deg * a0.y, a1.x * acc0.y + deg * a1.y);
    pk.y = packh2(a2.x * acc0.z + deg * a2.y, a3.x * acc0.w + deg * a3.y);
    *(uint2*)&g_aggh[node * 128 + lo4] = pk;
}

// ============================================================================
// init GEMM, split-tf32 (~fp32): g_hA = fp16( X[NN,75] @ W[75,128] )
// ============================================================================
#define IXS 44
#define IWS 132
__global__ void __launch_bounds__(256) k_init_tf32(const float* __restrict__ X,
                                                   const float* __restrict__ W) {
    __shared__ float Xs[128 * IXS];
    __shared__ float Ws[40 * IWS];
    int tid = threadIdx.x;
    int lane = tid & 31;
    int wid = tid >> 5;
    int mwarp = wid & 3, nwarp = wid >> 2;
    int rowBase = blockIdx.x * 128;
    int mBase = mwarp * 32, nBase = nwarp * 64;
    int frow = lane >> 2, fcol = lane & 3;

    float acc[2][8][4];
#pragma unroll
    for (int mt = 0; mt < 2; mt++)
#pragma unroll
        for (int nt = 0; nt < 8; nt++)
#pragma unroll
            for (int j = 0; j < 4; j++) acc[mt][nt][j] = 0.f;

    for (int k0 = 0; k0 < 80; k0 += 40) {
        for (int idx = tid; idx < 128 * 40; idx += 256) {
            int r = idx / 40, k = idx - r * 40;
            int gk = k0 + k;
            Xs[r * IXS + k] = (gk < 75) ? X[(rowBase + r) * 75 + gk] : 0.f;
        }
        for (int idx = tid; idx < 40 * 128; idx += 256) {
            int k = idx >> 7, n = idx & 127;
            int gk = k0 + k;
            Ws[k * IWS + n] = (gk < 75) ? W[gk * 128 + n] : 0.f;
        }
        __syncthreads();
#pragma unroll
        for (int kb = 0; kb < 40; kb += 8) {
            uint32_t ahi[2][4], alo[2][4];
#pragma unroll
            for (int mt = 0; mt < 2; mt++) {
                int r0 = mBase + mt * 16 + frow;
                split_tf32(Xs[r0 * IXS + kb + fcol],           ahi[mt][0], alo[mt][0]);
                split_tf32(Xs[(r0 + 8) * IXS + kb + fcol],     ahi[mt][1], alo[mt][1]);
                split_tf32(Xs[r0 * IXS + kb + fcol + 4],       ahi[mt][2], alo[mt][2]);
                split_tf32(Xs[(r0 + 8) * IXS + kb + fcol + 4], ahi[mt][3], alo[mt][3]);
            }
            uint32_t bhi[8][2], blo[8][2];
#pragma unroll
            for (int nt = 0; nt < 8; nt++) {
                int n = nBase + nt * 8 + frow;
                split_tf32(Ws[(kb + fcol) * IWS + n],     bhi[nt][0], blo[nt][0]);
                split_tf32(Ws[(kb + fcol + 4) * IWS + n], bhi[nt][1], blo[nt][1]);
            }
#pragma unroll
            for (int mt = 0; mt < 2; mt++)
#pragma unroll
                for (int nt = 0; nt < 8; nt++) {
                    mma_tf32(acc[mt][nt], ahi[mt], bhi[nt]);
                    mma_tf32(acc[mt][nt], alo[mt], bhi[nt]);
                    mma_tf32(acc[mt][nt], ahi[mt], blo[nt]);
                }
        }
        __syncthreads();
    }
#pragma unroll
    for (int mt = 0; mt < 2; mt++)
#pragma unroll
        for (int nt = 0; nt < 8; nt++) {
            int col = nBase + nt * 8 + fcol * 2;
            int r0 = rowBase + mBase + mt * 16 + frow;
            *(uint32_t*)&g_hA[r0 * 128 + col]       = packh2(acc[mt][nt][0], acc[mt][nt][1]);
            *(uint32_t*)&g_hA[(r0 + 8) * 128 + col] = packh2(acc[mt][nt][2], acc[mt][nt][3]);
        }
}

// ============================================================================
// Fused layer GEMM, all-fp16 operands, N-split (occupancy >= 2):
//   CTA: rows [rowBase, +128) x cols [colBase, +64)
//   C = relu(A1 @ W1 + b1) + relu( hfma2(s,x,t) @ W2 + b2 ) + BN stats
// Stage: A1 128x80B | X 128x80B | W1 64x80B | W2 64x80B = 30720 B
// ============================================================================
#define FA1_B   0
#define FX_B    10240
#define FW1_B   20480
#define FW2_B   25600
#define FSTG_B  30720
#define FBIAS1  (2 * FSTG_B / 4)       // float idx 15360
#define FBIAS2  (FBIAS1 + 64)
#define SH2_B   (2 * FSTG_B + 512)     // byte offset: 64 half2 s
#define TH2_B   (SH2_B + 256)          // 64 half2 t
#define SMEM_FUSED (TH2_B + 256 + 256)

__device__ __forceinline__ void f_issue(uint32_t sb, int st, int c, int tid, int rowBase,
                                        const __half* A1h, const __half* Xh,
                                        const __half* W1p, const __half* W2p) {
    uint32_t stb = sb + st * FSTG_B;
    int k0 = c * 32;
#pragma unroll
    for (int i = 0; i < 2; i++) {               // A1, X: 512 cp16 each
        int idx = i * 256 + tid;
        int r = idx >> 2, q = idx & 3;
        cp16(stb + FA1_B + r * 80 + q * 16, A1h + (rowBase + r) * 128 + k0 + q * 8);
        cp16(stb + FX_B + r * 80 + q * 16,  Xh + (rowBase + r) * 128 + k0 + q * 8);
    }
    {                                           // W1, W2: 256 cp16 each
        int r = tid >> 2, q = tid & 3;
        cp16(stb + FW1_B + r * 80 + q * 16, W1p + r * 128 + k0 + q * 8);
        cp16(stb + FW2_B + r * 80 + q * 16, W2p + r * 128 + k0 + q * 8);
    }
    CP_COMMIT();
}

__device__ __forceinline__ void f_compute(uint32_t sb, int st, int k0,
                                          int mBase, int nBase, int lane,
                                          const __half2* sh2, const __half2* th2,
                                          float acc1[2][4][4], float acc2[2][4][4]) {
    uint32_t stb = sb + st * FSTG_B;
    int g = lane >> 3, lr = lane & 7;
    int fcol = lane & 3;
    int arow = ((g & 1) << 3) + lr;
    int abyte = (g >> 1) << 4;
    int brow = ((g >> 1) << 3) + lr;
    int bbyte = (g & 1) << 4;

#pragma unroll
    for (int kb = 0; kb < 32; kb += 16) {
        // GC branch
        uint32_t a1[2][4], bf1[2][4];
#pragma unroll
        for (int mt = 0; mt < 2; mt++) {
            uint32_t base = stb + FA1_B + (uint32_t)(mBase + mt * 16 + arow) * 80 + kb * 2 + abyte;
            ldsm_x4(a1[mt], base);
        }
#pragma unroll
        for (int p = 0; p < 2; p++) {
            uint32_t base = stb + FW1_B + (uint32_t)(nBase + p * 16 + brow) * 80 + kb * 2 + bbyte;
            ldsm_x4(bf1[p], base);
        }
#pragma unroll
        for (int mt = 0; mt < 2; mt++)
#pragma unroll
            for (int p = 0; p < 2; p++) {
                mma_f16(acc1[mt][2 * p],     a1[mt], &bf1[p][0]);
                mma_f16(acc1[mt][2 * p + 1], a1[mt], &bf1[p][2]);
            }

        // RES branch (affine on fragments)
        uint32_t ax[2][4], bf2[2][4];
#pragma unroll
        for (int mt = 0; mt < 2; mt++) {
            uint32_t base = stb + FX_B + (uint32_t)(mBase + mt * 16 + arow) * 80 + kb * 2 + abyte;
            ldsm_x4(ax[mt], base);
        }
        int i2 = (k0 + kb) / 2 + fcol;
        __half2 sA = sh2[i2],     tA = th2[i2];
        __half2 sB = sh2[i2 + 4], tB = th2[i2 + 4];
#pragma unroll
        for (int mt = 0; mt < 2; mt++) {
            __half2 v;
            v = __hfma2(*(__half2*)&ax[mt][0], sA, tA); ax[mt][0] = *(uint32_t*)&v;
            v = __hfma2(*(__half2*)&ax[mt][1], sA, tA); ax[mt][1] = *(uint32_t*)&v;
            v = __hfma2(*(__half2*)&ax[mt][2], sB, tB); ax[mt][2] = *(uint32_t*)&v;
            v = __hfma2(*(__half2*)&ax[mt][3], sB, tB); ax[mt][3] = *(uint32_t*)&v;
        }
#pragma unroll
        for (int p = 0; p < 2; p++) {
            uint32_t base = stb + FW2_B + (uint32_t)(nBase + p * 16 + brow) * 80 + kb * 2 + bbyte;
            ldsm_x4(bf2[p], base);
        }
#pragma unroll
        for (int mt = 0; mt < 2; mt++)
#pragma unroll
            for (int p = 0; p < 2; p++) {
                mma_f16(acc2[mt][2 * p],     ax[mt], &bf2[p][0]);
                mma_f16(acc2[mt][2 * p + 1], ax[mt], &bf2[p][2]);
            }
    }
}

__global__ void __launch_bounds__(256, 2) k_layer_fused(
    const __half* __restrict__ A1h, const __half* __restrict__ Xh,
    const __half* __restrict__ W1h, const __half* __restrict__ W2h,
    const float* __restrict__ b1, const float* __restrict__ b2,
    const float* __restrict__ sumPrev, const float* __restrict__ sumsqPrev,
    const float* __restrict__ gammaPrev, const float* __restrict__ betaPrev, int useAff,
    float* __restrict__ Cf, __half* __restrict__ Ch, int outHalf,
    float* __restrict__ sumP, float* __restrict__ sumsqP) {
    extern __shared__ char smc[];
    float* smf = (float*)smc;
    uint32_t sb = smem_u32(smc);
    int tid = threadIdx.x;
    int lane = tid & 31;
    int wid = tid >> 5;
    int mwarp = wid & 3, nwarp = wid >> 2;
    int rowBase = (blockIdx.x >> 1) * 128;
    int colBase = (blockIdx.x & 1) * 64;
    int mBase = mwarp * 32, nBase = nwarp * 32;
    int frow = lane >> 2, fcol = lane & 3;

    const __half* W1p = W1h + colBase * 128;
    const __half* W2p = W2h + colBase * 128;

    if (tid < 64) {
        smf[FBIAS1 + tid] = b1[colBase + tid];
        smf[FBIAS2 + tid] = b2[colBase + tid];
        // BN affine as half2 pairs for features (2*tid, 2*tid+1)
        float s0 = 1.f, t0 = 0.f, s1 = 1.f, t1 = 0.f;
        if (useAff) {
            const float invN = 1.f / (float)NN;
            int f0 = 2 * tid, f1 = 2 * tid + 1;
            float mu0 = sumPrev[f0] * invN;
            float var0 = sumsqPrev[f0] * invN - mu0 * mu0;
            s0 = gammaPrev[f0] * rsqrtf(var0 + EPS_BN);
            t0 = betaPrev[f0] - mu0 * s0;
            float mu1 = sumPrev[f1] * invN;
            float var1 = sumsqPrev[f1] * invN - mu1 * mu1;
            s1 = gammaPrev[f1] * rsqrtf(var1 + EPS_BN);
            t1 = betaPrev[f1] - mu1 * s1;
        }
        ((__half2*)(smc + SH2_B))[tid] = __floats2half2_rn(s0, s1);
        ((__half2*)(smc + TH2_B))[tid] = __floats2half2_rn(t0, t1);
    }
    const __half2* sh2 = (const __half2*)(smc + SH2_B);
    const __half2* th2 = (const __half2*)(smc + TH2_B);

    float acc1[2][4][4], acc2[2][4][4];
#pragma unroll
    for (int mt = 0; mt < 2; mt++)
#pragma unroll
        for (int nt = 0; nt < 4; nt++)
#pragma unroll
            for (int j = 0; j < 4; j++) { acc1[mt][nt][j] = 0.f; acc2[mt][nt][j] = 0.f; }

    f_issue(sb, 0, 0, tid, rowBase, A1h, Xh, W1p, W2p);
    f_issue(sb, 1, 1, tid, rowBase, A1h, Xh, W1p, W2p);

    CP_WAIT(1); __syncthreads();
    f_compute(sb, 0, 0, mBase, nBase, lane, sh2, th2, acc1, acc2);
    __syncthreads();
    f_issue(sb, 0, 2, tid, rowBase, A1h, Xh, W1p, W2p);

    CP_WAIT(1); __syncthreads();
    f_compute(sb, 1, 32, mBase, nBase, lane, sh2, th2, acc1, acc2);
    __syncthreads();
    f_issue(sb, 1, 3, tid, rowBase, A1h, Xh, W1p, W2p);

    CP_WAIT(1); __syncthreads();
    f_compute(sb, 0, 64, mBase, nBase, lane, sh2, th2, acc1, acc2);
    __syncthreads();

    CP_WAIT(0); __syncthreads();
    f_compute(sb, 1, 96, mBase, nBase, lane, sh2, th2, acc1, acc2);

    // epilogue
    const float* bs1 = smf + FBIAS1;
    const float* bs2 = smf + FBIAS2;
#pragma unroll
    for (int nt = 0; nt < 4; nt++) {
        int lcol = nBase + nt * 8 + fcol * 2;
        int gcol = colBase + lcol;
        float B10 = bs1[lcol], B11 = bs1[lcol + 1];
        float B20 = bs2[lcol], B21 = bs2[lcol + 1];
        float s0 = 0.f, s1 = 0.f, q0 = 0.f, q1 = 0.f;
#pragma unroll
        for (int mt = 0; mt < 2; mt++) {
            int r0 = rowBase + mBase + mt * 16 + frow;
            int r1 = r0 + 8;
            float u0 = acc1[mt][nt][0] + B10; u0 = u0 > 0.f ? u0 : 0.f;
            float u1 = acc1[mt][nt][1] + B11; u1 = u1 > 0.f ? u1 : 0.f;
            float u2 = acc1[mt][nt][2] + B10; u2 = u2 > 0.f ? u2 : 0.f;
            float u3 = acc1[mt][nt][3] + B11; u3 = u3 > 0.f ? u3 : 0.f;
            float v0 = acc2[mt][nt][0] + B20; v0 = v0 > 0.f ? v0 : 0.f;
            float v1 = acc2[mt][nt][1] + B21; v1 = v1 > 0.f ? v1 : 0.f;
            float v2 = acc2[mt][nt][2] + B20; v2 = v2 > 0.f ? v2 : 0.f;
            float v3 = acc2[mt][nt][3] + B21; v3 = v3 > 0.f ? v3 : 0.f;
            float o0 = u0 + v0, o1 = u1 + v1, o2 = u2 + v2, o3 = u3 + v3;
            if (outHalf) {
                *(uint32_t*)&Ch[r0 * 128 + gcol] = packh2(o0, o1);
                *(uint32_t*)&Ch[r1 * 128 + gcol] = packh2(o2, o3);
            } else {
                *(float2*)&Cf[r0 * 128 + gcol] = make_float2(o0, o1);
                *(float2*)&Cf[r1 * 128 + gcol] = make_float2(o2, o3);
            }
            s0 += o0 + o2; s1 += o1 + o3;
            q0 += o0 * o0 + o2 * o2; q1 += o1 * o1 + o3 * o3;
        }
#pragma unroll
        for (int m = 4; m <= 16; m <<= 1) {
            s0 += __shfl_xor_sync(0xffffffff, s0, m);
            s1 += __shfl_xor_sync(0xffffffff, s1, m);
            q0 += __shfl_xor_sync(0xffffffff, q0, m);
            q1 += __shfl_xor_sync(0xffffffff, q1, m);
        }
        if (frow == 0) {
            atomicAdd(&sumP[gcol], s0);
            atomicAdd(&sumP[gcol + 1], s1);
            atomicAdd(&sumsqP[gcol], q0);
            atomicAdd(&sumsqP[gcol + 1], q1);
        }
    }
}

// ============================================================================
// final BN normalize (fp32 input)
// ============================================================================
__global__ void __launch_bounds__(256) k_bn_norm(const float* __restrict__ x,
                                                 float* __restrict__ out,
                                                 const float* __restrict__ gamma,
                                                 const float* __restrict__ beta,
                                                 const float* __restrict__ sumP,
                                                 const float* __restrict__ sumsqP) {
    int idx = blockIdx.x * blockDim.x + threadIdx.x;
    int base = idx * 4;
    if (base >= NN * DD) return;
    int c = base & 127;
    const float invN = 1.f / (float)NN;
    float4 v = *(const float4*)&x[base];
    float xv[4] = {v.x, v.y, v.z, v.w};
    float o[4];
#pragma unroll
    for (int j = 0; j < 4; j++) {
        float mu = sumP[c + j] * invN;
        float var = sumsqP[c + j] * invN - mu * mu;
        float rs = rsqrtf(var + EPS_BN);
        o[j] = gamma[c + j] * (xv[j] - mu) * rs + beta[c + j];
    }
    *(float4*)&out[base] = make_float4(o[0], o[1], o[2], o[3]);
}

// ============================================================================
extern "C" void kernel_launch(void* const* d_in, const int* in_sizes, int n_in,
                              void* d_out, int out_size) {
    const float* X     = (const float*)d_in[0];
    const int*   src   = (const int*)d_in[1];
    const int*   dst   = (const int*)d_in[2];
    const float* Winit = (const float*)d_in[3];
    const float* Wg    = (const float*)d_in[4];
    const float* bg    = (const float*)d_in[5];
    const float* Wr    = (const float*)d_in[6];
    const float* br    = (const float*)d_in[7];
    const float* gamma = (const float*)d_in[8];
    const float* beta  = (const float*)d_in[9];
    float* out = (float*)d_out;

    void *pa, *pb, *pagg, *ptmp, *ps, *pq, *pwth;
    cudaGetSymbolAddress(&pa, g_hA);
    cudaGetSymbolAddress(&pb, g_hB);
    cudaGetSymbolAddress(&pagg, g_aggh);
    cudaGetSymbolAddress(&ptmp, g_tmp);
    cudaGetSymbolAddress(&ps, g_sum);
    cudaGetSymbolAddress(&pq, g_sumsq);
    cudaGetSymbolAddress(&pwth, g_Wth);
    __half* hA   = (__half*)pa;
    __half* hB   = (__half*)pb;
    __half* aggh = (__half*)pagg;
    float*  tmp  = (float*)ptmp;
    float*  sum  = (float*)ps;
    float*  sumq = (float*)pq;
    __half* Wth  = (__half*)pwth;

    cudaFuncSetAttribute(k_layer_fused, cudaFuncAttributeMaxDynamicSharedMemorySize,
                         SMEM_FUSED);

    const int edgeGrid = EE / 256;
    const int warpGrid = (NN * 32) / 256;
    const int gemmGrid = NN / 128;
    const int fusedGrid = gemmGrid * 2;
    const int normGrid = (NN * DD / 4 + 255) / 256;

    k_zero_prep<<<384, 256>>>(Wg, Wr);
    k_hist<<<edgeGrid, 256>>>(dst);
    k_scan_lb<<<145, 512>>>();
    k_fill<<<edgeGrid, 256>>>(src, dst);
    k_init_tf32<<<gemmGrid, 256>>>(X, Winit);

    __half* hIn[NLAYERS]  = {hA, hB, hA};
    __half* hOut[NLAYERS] = {hB, hA, (__half*)0};
    for (int l = 0; l < NLAYERS; l++) {
        const float* sPrev = sum + (l - 1) * DD;
        const float* qPrev = sumq + (l - 1) * DD;
        const float* gPrev = gamma + (l - 1) * DD;
        const float* bPrev = beta + (l - 1) * DD;
        int useAff = (l > 0) ? 1 : 0;
        if (!useAff) { sPrev = sum; qPrev = sumq; gPrev = gamma; bPrev = beta; }
        int outHalf = (l < NLAYERS - 1) ? 1 : 0;
        k_gather<<<warpGrid, 256>>>(hIn[l], sPrev, qPrev, gPrev, bPrev, useAff);
        k_layer_fused<<<fusedGrid, 256, SMEM_FUSED>>>(
            aggh, hIn[l],
            Wth + (l * 2 + 0) * DD * DD, Wth + (l * 2 + 1) * DD * DD,
            bg + l * DD, br + l * DD,
            sPrev, qPrev, gPrev, bPrev, useAff,
            tmp, hOut[l], outHalf,
            sum + l * DD, sumq + l * DD);
    }
    k_bn_norm<<<normGrid, 256>>>(tmp, out, gamma + 2 * DD, beta + 2 * DD,
                                 sum + 2 * DD, sumq + 2 * DD);
}